// round 17
// baseline (speedup 1.0000x reference)
#include <cuda_runtime.h>

#define NN 50000
#define NE 800000
#define NET (NN + NE)
#define NB  ((NN + 255) / 256)

typedef unsigned long long ull;

// ---------------- scratch (no allocs allowed) ----------------
__device__ int    d_deg[NN];        // zero-init; reset to 0 by k_scan3
__device__ int    d_rowptr[NN + 1];
__device__ int    d_next[NN];
__device__ int    d_part[NB];
__device__ __align__(16) int2 d_csr[NET];      // {src, float_bits(edge_attr)}
__device__ double d_attr_sum;       // zero-init; reset by k_fill

__device__ __align__(16) float d_xl1[NN * 128];
__device__ __align__(16) float d_xr1[NN * 128];
__device__ __align__(16) float d_h1 [NN * 128];
__device__ __align__(16) float d_xl2[NN * 64];
__device__ __align__(16) float d_xr2[NN * 64];

// packed f32x2 ops (fp32 exact, lo/hi lanes independent)
#define FMA2(d, a, b) asm("fma.rn.f32x2 %0, %1, %2, %0;" : "+l"(d) : "l"(a), "l"(b))
#define UNPACK2(lo, hi, p) asm("mov.b64 {%0, %1}, %2;" : "=f"(lo), "=f"(hi) : "l"(p))
__device__ __forceinline__ ull pack2(float lo, float hi) {
    ull r; asm("mov.b64 %0, {%1, %2};" : "=l"(r) : "f"(lo), "f"(hi)); return r;
}
__device__ __forceinline__ ull add2_(ull a, ull b) {
    ull r; asm("add.rn.f32x2 %0, %1, %2;" : "=l"(r) : "l"(a), "l"(b)); return r;
}
__device__ __forceinline__ ull mul2_(ull a, ull b) {
    ull r; asm("mul.rn.f32x2 %0, %1, %2;" : "=l"(r) : "l"(a), "l"(b)); return r;
}
__device__ __forceinline__ ull fma2_(ull a, ull b, ull c) {
    ull r; asm("fma.rn.f32x2 %0, %1, %2, %3;" : "=l"(r) : "l"(a), "l"(b), "l"(c)); return r;
}
#define LOG2E 1.4426950408889634f
#define ABSMASK 0x7FFFFFFF7FFFFFFFULL
// leaky_relu(z) = max(z, 0.2z) = 0.6z + 0.4|z| (exact branch algebra, packed)
__device__ __forceinline__ ull leaky2(ull z, ull c06, ull c04) {
    return fma2_(c04, z & ABSMASK, mul2_(c06, z));
}

// ---------------- CSR build ----------------
__global__ void k_count(const int* __restrict__ ei, const float* __restrict__ eattr) {
    int e = blockIdx.x * blockDim.x + threadIdx.x;
    float v = 0.f;
    if (e < NE) {
        atomicAdd(&d_deg[ei[NE + e]], 1);
        v = eattr[e];
    }
    for (int o = 16; o; o >>= 1) v += __shfl_xor_sync(0xffffffffu, v, o);
    __shared__ float ws[8];
    int lane = threadIdx.x & 31, wid = threadIdx.x >> 5;
    if (lane == 0) ws[wid] = v;
    __syncthreads();
    if (threadIdx.x == 0) {
        float s = 0.f;
        for (int w = 0; w < (int)(blockDim.x >> 5); w++) s += ws[w];
        atomicAdd(&d_attr_sum, (double)s);
    }
}

__global__ void k_scan1() {
    int n = blockIdx.x * 256 + threadIdx.x;
    int v = (n < NN) ? d_deg[n] + 1 : 0;
    for (int o = 16; o; o >>= 1) v += __shfl_xor_sync(0xffffffffu, v, o);
    __shared__ int ws[8];
    int lane = threadIdx.x & 31, wid = threadIdx.x >> 5;
    if (lane == 0) ws[wid] = v;
    __syncthreads();
    if (threadIdx.x == 0) {
        int s = 0;
        for (int w = 0; w < 8; w++) s += ws[w];
        d_part[blockIdx.x] = s;
    }
}

__global__ void k_scan2() {   // single block, 256 threads; NB <= 256
    int t = threadIdx.x, lane = t & 31, wid = t >> 5;
    int v = (t < NB) ? d_part[t] : 0;
    int inc = v;
    for (int o = 1; o < 32; o <<= 1) {
        int y = __shfl_up_sync(0xffffffffu, inc, o);
        if (lane >= o) inc += y;
    }
    __shared__ int ws[8];
    if (lane == 31) ws[wid] = inc;
    __syncthreads();
    if (wid == 0) {
        int w = (lane < 8) ? ws[lane] : 0;
        for (int o = 1; o < 8; o <<= 1) {
            int y = __shfl_up_sync(0xffffffffu, w, o);
            if (lane >= o) w += y;
        }
        if (lane < 8) ws[lane] = w;
    }
    __syncthreads();
    int excl = inc - v + (wid ? ws[wid - 1] : 0);
    if (t < NB) d_part[t] = excl;
    if (t == 0) d_rowptr[NN] = ws[7];
}

__global__ void k_scan3() {
    int b = blockIdx.x, t = threadIdx.x, lane = t & 31, wid = t >> 5;
    int n = b * 256 + t;
    int orig = (n < NN) ? d_deg[n] + 1 : 0;
    int inc = orig;
    for (int o = 1; o < 32; o <<= 1) {
        int y = __shfl_up_sync(0xffffffffu, inc, o);
        if (lane >= o) inc += y;
    }
    __shared__ int ws[8];
    if (lane == 31) ws[wid] = inc;
    __syncthreads();
    if (wid == 0) {
        int w = (lane < 8) ? ws[lane] : 0;
        for (int o = 1; o < 8; o <<= 1) {
            int y = __shfl_up_sync(0xffffffffu, w, o);
            if (lane >= o) w += y;
        }
        if (lane < 8) ws[lane] = w;
    }
    __syncthreads();
    if (n < NN) {
        int start = d_part[b] + inc - orig + (wid ? ws[wid - 1] : 0);
        float mean = (float)(d_attr_sum / (double)NE);
        d_rowptr[n] = start;
        d_next[n]   = start + 1;
        d_csr[start] = make_int2(n, __float_as_int(mean));   // self-loop
        d_deg[n] = 0;                                        // reset for next replay
    }
}

__global__ void k_fill(const int* __restrict__ ei, const float* __restrict__ eattr) {
    int e = blockIdx.x * blockDim.x + threadIdx.x;
    if (e == 0) d_attr_sum = 0.0;      // reset for next replay
    if (e >= NE) return;
    int src = ei[e], dst = ei[NE + e];
    int slot = atomicAdd(&d_next[dst], 1);
    d_csr[slot] = make_int2(src, __float_as_int(eattr[e]));
}

// ---------------- fused dual fp32 GEMM, FFMA2, paired-k LDS.128 (R11 exact) ----------------
#define ASTRIDE 132
__global__ void __launch_bounds__(256, 2) k_gemm(const float* __restrict__ A,
                                                 const float* __restrict__ Wl,
                                                 const float* __restrict__ Wr,
                                                 const float* __restrict__ bl,
                                                 const float* __restrict__ br,
                                                 float* __restrict__ Ol,
                                                 float* __restrict__ Or,
                                                 int rows, int ncols) {
    extern __shared__ float sm[];
    float* Ash = sm;                          // 128 x ASTRIDE
    ull*   Wq  = (ull*)(sm + 128 * ASTRIDE);  // 32 k4 x (64 col x 2 pair)
    int t  = threadIdx.x;
    int nyh = ncols >> 6;                     // y-tiles per matrix
    int half = (int)blockIdx.y >= nyh;
    const float* W    = half ? Wr : Wl;
    const float* bias = half ? br : bl;
    float*       O    = half ? Or : Ol;
    int rb = blockIdx.x * 128;
    int cb = ((int)blockIdx.y - (half ? nyh : 0)) * 64;

    const float4* A4 = (const float4*)A;
    for (int i = t; i < 128 * 32; i += 256) {
        int r = i >> 5, c4 = i & 31;
        int gr = rb + r;
        float4 v = (gr < rows) ? A4[gr * 32 + c4] : make_float4(0.f, 0.f, 0.f, 0.f);
        *(float4*)&Ash[r * ASTRIDE + c4 * 4] = v;
    }
    for (int i = t; i < 32 * 16; i += 256) {
        int k4 = i >> 4, c4 = (i & 15) * 4;
        float4 w0 = __ldg((const float4*)&W[(4 * k4    ) * ncols + cb + c4]);
        float4 w1 = __ldg((const float4*)&W[(4 * k4 + 1) * ncols + cb + c4]);
        float4 w2 = __ldg((const float4*)&W[(4 * k4 + 2) * ncols + cb + c4]);
        float4 w3 = __ldg((const float4*)&W[(4 * k4 + 3) * ncols + cb + c4]);
        ull* dst = Wq + k4 * 128 + c4 * 2;
        dst[0] = pack2(w0.x, w1.x);  dst[1] = pack2(w2.x, w3.x);
        dst[2] = pack2(w0.y, w1.y);  dst[3] = pack2(w2.y, w3.y);
        dst[4] = pack2(w0.z, w1.z);  dst[5] = pack2(w2.z, w3.z);
        dst[6] = pack2(w0.w, w1.w);  dst[7] = pack2(w2.w, w3.w);
    }
    __syncthreads();

    int tc = t & 15, tr = t >> 4;
    const float* arow  = &Ash[(tr * 8) * ASTRIDE];
    const ull*   wbase = Wq + tc * 2;

    ull acc[8][4];
#pragma unroll
    for (int r = 0; r < 8; r++)
#pragma unroll
        for (int c = 0; c < 4; c++) acc[r][c] = 0ULL;

#pragma unroll 2
    for (int k4 = 0; k4 < 32; k4++) {
        ulonglong2 wv[4];
#pragma unroll
        for (int c = 0; c < 4; c++)
            wv[c] = *(const ulonglong2*)(wbase + k4 * 128 + 32 * c);
#pragma unroll
        for (int r = 0; r < 8; r++) {
            ulonglong2 av = *(const ulonglong2*)(arow + r * ASTRIDE + 4 * k4);
            FMA2(acc[r][0], av.x, wv[0].x);
            FMA2(acc[r][1], av.x, wv[1].x);
            FMA2(acc[r][2], av.x, wv[2].x);
            FMA2(acc[r][3], av.x, wv[3].x);
            FMA2(acc[r][0], av.y, wv[0].y);
            FMA2(acc[r][1], av.y, wv[1].y);
            FMA2(acc[r][2], av.y, wv[2].y);
            FMA2(acc[r][3], av.y, wv[3].y);
        }
    }

    float bvc[4];
#pragma unroll
    for (int c = 0; c < 4; c++) bvc[c] = __ldg(bias + cb + tc + 16 * c);
#pragma unroll
    for (int r = 0; r < 8; r++) {
        int row = rb + tr * 8 + r;
        if (row < rows) {
            float* orow = O + (size_t)row * ncols + cb + tc;
#pragma unroll
            for (int c = 0; c < 4; c++) {
                float lo, hi;
                UNPACK2(lo, hi, acc[r][c]);
                orow[16 * c] = lo + hi + bvc[c];
            }
        }
    }
}

// ---------------- GATv2 layer 1: heads=4, D=32, concat, ELU; packed f32x2 ----------------
__global__ void __launch_bounds__(256) k_gat1(const float* __restrict__ xl,
                                              const float* __restrict__ xr,
                                              const float* __restrict__ we,
                                              const float* __restrict__ att,
                                              const float* __restrict__ bias,
                                              float* __restrict__ out) {
    int w = (blockIdx.x * blockDim.x + threadIdx.x) >> 5;
    if (w >= NN) return;
    int lane = threadIdx.x & 31;
    int n = w;

    const ull c06 = pack2(0.6f, 0.6f), c04 = pack2(0.4f, 0.4f);

    ulonglong2 xrp = ((const ulonglong2*)(xr + (size_t)n * 128))[lane];
    float4 wef = __ldg((const float4*)we  + lane);
    float4 atf = __ldg((const float4*)att + lane);
    ull we01 = pack2(wef.x, wef.y), we23 = pack2(wef.z, wef.w);
    ull at01 = pack2(atf.x * LOG2E, atf.y * LOG2E);
    ull at23 = pack2(atf.z * LOG2E, atf.w * LOG2E);

    int d0 = d_rowptr[n], d1 = d_rowptr[n + 1];

    float mx = -1e30f, den = 0.f;
    ull acc01 = 0ULL, acc23 = 0ULL;

    const ulonglong2* XL = (const ulonglong2*)xl;   // row (128 floats) = 32 ulonglong2

    int i = d0;
    for (; i + 1 < d1; i += 2) {
        int2 ea = d_csr[i];
        int2 eb = d_csr[i + 1];
        ull eav2a = pack2(__int_as_float(ea.y), __int_as_float(ea.y));
        ull eav2b = pack2(__int_as_float(eb.y), __int_as_float(eb.y));
        ulonglong2 xa = __ldg(XL + (size_t)ea.x * 32 + lane);
        ulonglong2 xb = __ldg(XL + (size_t)eb.x * 32 + lane);

        ull la01 = leaky2(fma2_(eav2a, we01, add2_(xa.x, xrp.x)), c06, c04);
        ull la23 = leaky2(fma2_(eav2a, we23, add2_(xa.y, xrp.y)), c06, c04);
        ull lb01 = leaky2(fma2_(eav2b, we01, add2_(xb.x, xrp.x)), c06, c04);
        ull lb23 = leaky2(fma2_(eav2b, we23, add2_(xb.y, xrp.y)), c06, c04);

        ull da = fma2_(la23, at23, mul2_(la01, at01));
        ull db = fma2_(lb23, at23, mul2_(lb01, at01));
        float dal, dah, dbl, dbh;
        UNPACK2(dal, dah, da);
        UNPACK2(dbl, dbh, db);
        float va = dal + dah, vb = dbl + dbh;
        va += __shfl_xor_sync(0xffffffffu, va, 4);
        vb += __shfl_xor_sync(0xffffffffu, vb, 4);
        va += __shfl_xor_sync(0xffffffffu, va, 2);
        vb += __shfl_xor_sync(0xffffffffu, vb, 2);
        va += __shfl_xor_sync(0xffffffffu, va, 1);
        vb += __shfl_xor_sync(0xffffffffu, vb, 1);

        float nm = fmaxf(mx, fmaxf(va, vb));
        float sc  = exp2f(mx - nm);
        float exa = exp2f(va - nm);
        float exb = exp2f(vb - nm);
        den = den * sc + exa + exb;
        ull sc2  = pack2(sc, sc);
        ull exa2 = pack2(exa, exa);
        ull exb2 = pack2(exb, exb);
        acc01 = fma2_(acc01, sc2, fma2_(xa.x, exa2, mul2_(xb.x, exb2)));
        acc23 = fma2_(acc23, sc2, fma2_(xa.y, exa2, mul2_(xb.y, exb2)));
        mx = nm;
    }
    if (i < d1) {
        int2 e = d_csr[i];
        ull eav2 = pack2(__int_as_float(e.y), __int_as_float(e.y));
        ulonglong2 xa = __ldg(XL + (size_t)e.x * 32 + lane);
        ull l01 = leaky2(fma2_(eav2, we01, add2_(xa.x, xrp.x)), c06, c04);
        ull l23 = leaky2(fma2_(eav2, we23, add2_(xa.y, xrp.y)), c06, c04);
        ull d2 = fma2_(l23, at23, mul2_(l01, at01));
        float dl, dh;
        UNPACK2(dl, dh, d2);
        float v = dl + dh;
        v += __shfl_xor_sync(0xffffffffu, v, 4);
        v += __shfl_xor_sync(0xffffffffu, v, 2);
        v += __shfl_xor_sync(0xffffffffu, v, 1);
        float nm = fmaxf(mx, v);
        float sc = exp2f(mx - nm);
        float ex = exp2f(v - nm);
        den = den * sc + ex;
        ull sc2 = pack2(sc, sc), ex2 = pack2(ex, ex);
        acc01 = fma2_(acc01, sc2, mul2_(xa.x, ex2));
        acc23 = fma2_(acc23, sc2, mul2_(xa.y, ex2));
    }

    float inv = 1.f / den;
    float4 b4 = __ldg((const float4*)bias + lane);
    float a0, a1, a2, a3;
    UNPACK2(a0, a1, acc01);
    UNPACK2(a2, a3, acc23);
    float4 o;
    o.x = a0 * inv + b4.x;  o.x = (o.x > 0.f) ? o.x : expm1f(o.x);
    o.y = a1 * inv + b4.y;  o.y = (o.y > 0.f) ? o.y : expm1f(o.y);
    o.z = a2 * inv + b4.z;  o.z = (o.z > 0.f) ? o.z : expm1f(o.z);
    o.w = a3 * inv + b4.w;  o.w = (o.w > 0.f) ? o.w : expm1f(o.w);
    ((float4*)(out + (size_t)n * 128))[lane] = o;
}

// ---------------- GATv2 layer 2 (heads=2, mean) + ELU + classifier; packed f32x2 ----------------
__global__ void __launch_bounds__(256) k_gat2(const float* __restrict__ xl,
                                              const float* __restrict__ xr,
                                              const float* __restrict__ we,
                                              const float* __restrict__ att,
                                              const float* __restrict__ bias,
                                              const float* __restrict__ wc,
                                              const float* __restrict__ bc,
                                              float* __restrict__ out) {
    int w = (blockIdx.x * blockDim.x + threadIdx.x) >> 5;
    if (w >= NN) return;
    int lane = threadIdx.x & 31;
    int n = w;

    const ull c06 = pack2(0.6f, 0.6f), c04 = pack2(0.4f, 0.4f);

    ull xrp = ((const ull*)(xr + (size_t)n * 64))[lane];
    float2 wef = __ldg((const float2*)we  + lane);
    float2 atf = __ldg((const float2*)att + lane);
    ull we2 = pack2(wef.x, wef.y);
    ull at2 = pack2(atf.x * LOG2E, atf.y * LOG2E);

    int d0 = d_rowptr[n], d1 = d_rowptr[n + 1];

    float mx = -1e30f, den = 0.f;
    ull acc2 = 0ULL;

    const ull* XL = (const ull*)xl;   // row (64 floats) = 32 ull

    int i = d0;
    for (; i + 1 < d1; i += 2) {
        int2 ea = d_csr[i];
        int2 eb = d_csr[i + 1];
        ull eav2a = pack2(__int_as_float(ea.y), __int_as_float(ea.y));
        ull eav2b = pack2(__int_as_float(eb.y), __int_as_float(eb.y));
        ull xa = __ldg(XL + (size_t)ea.x * 32 + lane);
        ull xb = __ldg(XL + (size_t)eb.x * 32 + lane);

        ull la = leaky2(fma2_(eav2a, we2, add2_(xa, xrp)), c06, c04);
        ull lb = leaky2(fma2_(eav2b, we2, add2_(xb, xrp)), c06, c04);
        ull da = mul2_(la, at2);
        ull db = mul2_(lb, at2);
        float dal, dah, dbl, dbh;
        UNPACK2(dal, dah, da);
        UNPACK2(dbl, dbh, db);
        float va = dal + dah, vb = dbl + dbh;
        va += __shfl_xor_sync(0xffffffffu, va, 8);
        vb += __shfl_xor_sync(0xffffffffu, vb, 8);
        va += __shfl_xor_sync(0xffffffffu, va, 4);
        vb += __shfl_xor_sync(0xffffffffu, vb, 4);
        va += __shfl_xor_sync(0xffffffffu, va, 2);
        vb += __shfl_xor_sync(0xffffffffu, vb, 2);
        va += __shfl_xor_sync(0xffffffffu, va, 1);
        vb += __shfl_xor_sync(0xffffffffu, vb, 1);

        float nm = fmaxf(mx, fmaxf(va, vb));
        float sc  = exp2f(mx - nm);
        float exa = exp2f(va - nm);
        float exb = exp2f(vb - nm);
        den = den * sc + exa + exb;
        acc2 = fma2_(acc2, pack2(sc, sc),
                     fma2_(xa, pack2(exa, exa), mul2_(xb, pack2(exb, exb))));
        mx = nm;
    }
    if (i < d1) {
        int2 e = d_csr[i];
        ull eav2 = pack2(__int_as_float(e.y), __int_as_float(e.y));
        ull xa = __ldg(XL + (size_t)e.x * 32 + lane);
        ull l = leaky2(fma2_(eav2, we2, add2_(xa, xrp)), c06, c04);
        ull d2 = mul2_(l, at2);
        float dl, dh;
        UNPACK2(dl, dh, d2);
        float v = dl + dh;
        v += __shfl_xor_sync(0xffffffffu, v, 8);
        v += __shfl_xor_sync(0xffffffffu, v, 4);
        v += __shfl_xor_sync(0xffffffffu, v, 2);
        v += __shfl_xor_sync(0xffffffffu, v, 1);
        float nm = fmaxf(mx, v);
        float sc = exp2f(mx - nm);
        float ex = exp2f(v - nm);
        den = den * sc + ex;
        acc2 = fma2_(acc2, pack2(sc, sc), mul2_(xa, pack2(ex, ex)));
    }

    float inv = 1.f / den;
    float a0, a1;
    UNPACK2(a0, a1, acc2);
    float m0 = a0 * inv, m1 = a1 * inv;
    m0 = 0.5f * (m0 + __shfl_xor_sync(0xffffffffu, m0, 16));
    m1 = 0.5f * (m1 + __shfl_xor_sync(0xffffffffu, m1, 16));

    int dl2 = lane & 15;
    float2 b2 = __ldg((const float2*)bias + dl2);
    float t0 = m0 + b2.x;  t0 = (t0 > 0.f) ? t0 : expm1f(t0);
    float t1 = m1 + b2.y;  t1 = (t1 > 0.f) ? t1 : expm1f(t1);

    float4 wA0 = __ldg((const float4*)wc + dl2 * 4 + 0);
    float4 wA1 = __ldg((const float4*)wc + dl2 * 4 + 1);
    float4 wB0 = __ldg((const float4*)wc + dl2 * 4 + 2);
    float4 wB1 = __ldg((const float4*)wc + dl2 * 4 + 3);
    float p0 = t0 * wA0.x + t1 * wB0.x;
    float p1 = t0 * wA0.y + t1 * wB0.y;
    float p2 = t0 * wA0.z + t1 * wB0.z;
    float p3 = t0 * wA0.w + t1 * wB0.w;
    float p4 = t0 * wA1.x + t1 * wB1.x;
    float p5 = t0 * wA1.y + t1 * wB1.y;
    float p6 = t0 * wA1.z + t1 * wB1.z;
    float p7 = t0 * wA1.w + t1 * wB1.w;
    for (int o = 16; o; o >>= 1) {
        p0 += __shfl_xor_sync(0xffffffffu, p0, o);
        p1 += __shfl_xor_sync(0xffffffffu, p1, o);
        p2 += __shfl_xor_sync(0xffffffffu, p2, o);
        p3 += __shfl_xor_sync(0xffffffffu, p3, o);
        p4 += __shfl_xor_sync(0xffffffffu, p4, o);
        p5 += __shfl_xor_sync(0xffffffffu, p5, o);
        p6 += __shfl_xor_sync(0xffffffffu, p6, o);
        p7 += __shfl_xor_sync(0xffffffffu, p7, o);
    }
    if (lane == 0) {
        float4 o0 = make_float4(0.5f * p0 + __ldg(bc + 0), 0.5f * p1 + __ldg(bc + 1),
                                0.5f * p2 + __ldg(bc + 2), 0.5f * p3 + __ldg(bc + 3));
        float4 o1 = make_float4(0.5f * p4 + __ldg(bc + 4), 0.5f * p5 + __ldg(bc + 5),
                                0.5f * p6 + __ldg(bc + 6), 0.5f * p7 + __ldg(bc + 7));
        *(float4*)&out[(size_t)n * 8]     = o0;
        *(float4*)&out[(size_t)n * 8 + 4] = o1;
    }
}

// ---------------- launch ----------------
extern "C" void kernel_launch(void* const* d_in, const int* in_sizes, int n_in,
                              void* d_out, int out_size) {
    const float* x     = (const float*)d_in[0];
    const int*   ei    = (const int*)  d_in[1];
    const float* eattr = (const float*)d_in[2];
    const float* w1l   = (const float*)d_in[3];
    const float* b1l   = (const float*)d_in[4];
    const float* w1r   = (const float*)d_in[5];
    const float* b1r   = (const float*)d_in[6];
    const float* w1e   = (const float*)d_in[7];
    const float* att1  = (const float*)d_in[8];
    const float* bias1 = (const float*)d_in[9];
    const float* w2l   = (const float*)d_in[10];
    const float* b2l   = (const float*)d_in[11];
    const float* w2r   = (const float*)d_in[12];
    const float* b2r   = (const float*)d_in[13];
    const float* w2e   = (const float*)d_in[14];
    const float* att2  = (const float*)d_in[15];
    const float* bias2 = (const float*)d_in[16];
    const float* wc    = (const float*)d_in[17];
    const float* bc    = (const float*)d_in[18];
    float* out = (float*)d_out;

    void *pxl1, *pxr1, *ph1, *pxl2, *pxr2;
    cudaGetSymbolAddress(&pxl1, d_xl1);
    cudaGetSymbolAddress(&pxr1, d_xr1);
    cudaGetSymbolAddress(&ph1,  d_h1);
    cudaGetSymbolAddress(&pxl2, d_xl2);
    cudaGetSymbolAddress(&pxr2, d_xr2);

    static cudaStream_t s1 = nullptr;
    static cudaEvent_t ev_fork = nullptr, ev_join = nullptr;
    if (s1 == nullptr) {
        cudaStreamCreateWithFlags(&s1, cudaStreamNonBlocking);
        cudaEventCreateWithFlags(&ev_fork, cudaEventDisableTiming);
        cudaEventCreateWithFlags(&ev_join, cudaEventDisableTiming);
    }

    size_t smem = (size_t)128 * ASTRIDE * sizeof(float) + (size_t)32 * 128 * sizeof(ull);
    cudaFuncSetAttribute(k_gemm, cudaFuncAttributeMaxDynamicSharedMemorySize, (int)smem);

    // fork: CSR build on s1, concurrent with layer-1 GEMM on the main stream.
    cudaEventRecord(ev_fork, 0);
    cudaStreamWaitEvent(s1, ev_fork, 0);

    k_count<<<(NE + 255) / 256, 256, 0, s1>>>(ei, eattr);   // idx 0
    k_scan1<<<NB, 256, 0, s1>>>();                          // idx 1
    k_scan2<<<1, 256, 0, s1>>>();                           // idx 2

    dim3 g1((NN + 127) / 128, 4);   // y: 0-1 -> w1l, 2-3 -> w1r
    k_gemm<<<g1, 256, smem>>>(x, w1l, w1r, b1l, b1r,        // idx 3  <- ncu target
                              (float*)pxl1, (float*)pxr1, NN, 128);

    k_scan3<<<NB, 256, 0, s1>>>();                          // idx 4
    k_fill <<<(NE + 255) / 256, 256, 0, s1>>>(ei, eattr);   // idx 5
    cudaEventRecord(ev_join, s1);

    cudaStreamWaitEvent(0, ev_join, 0);

    int gat_blocks = (NN * 32 + 255) / 256;
    k_gat1<<<gat_blocks, 256>>>((const float*)pxl1, (const float*)pxr1,
                                w1e, att1, bias1, (float*)ph1);

    dim3 g2((NN + 127) / 128, 2);   // y: 0 -> w2l, 1 -> w2r
    k_gemm<<<g2, 256, smem>>>((const float*)ph1, w2l, w2r, b2l, b2r,
                              (float*)pxl2, (float*)pxr2, NN, 64);

    k_gat2<<<gat_blocks, 256>>>((const float*)pxl2, (const float*)pxr2,
                                w2e, att2, bias2, wc, bc, out);
}